// round 8
// baseline (speedup 1.0000x reference)
#include <cuda_runtime.h>
#include <math.h>

#define NPTS 50000
#define S    16
#define C    96
#define CP   97    // padded row: bank-conflict-free [s][*] access
#define G    6
#define CG   16    // C / G
#define TP   32    // points per block in k1
#define QKP  100   // padded q/k tile row in k1
#define P    4     // points per block in k2

// ---- scratch (no allocations allowed; __device__ globals are the sanctioned path)
__device__ float d_v [NPTS * C];   // v = feat@Wv + bv
__device__ float d_qW[NPTS * G];   // q @ Ww1
__device__ float d_kW[NPTS * G];   // k @ Ww1
__device__ float d_Wp2w1[C * G];   // Wp2 @ Ww1 (folded)
__device__ float d_bp2w1[G];       // bp2 @ Ww1 (folded)

__device__ __forceinline__ float bn_scale(float g) {
    return g * rsqrtf(1.0f + 1e-5f);
}

// ---------------------------------------------------------------------------
// Kernel 0: fold Wp2@Ww1 and bp2@Ww1 — parallel over 6 blocks
// ---------------------------------------------------------------------------
__global__ void k0_fold(const float* __restrict__ Wp2,
                        const float* __restrict__ bp2,
                        const float* __restrict__ Ww1) {
    int t = blockIdx.x * 128 + threadIdx.x;
    if (t < C * G) {
        int j = t / G, g = t % G;
        float acc = 0.f;
        #pragma unroll 8
        for (int c = 0; c < C; c++) acc += Wp2[j * C + c] * Ww1[c * G + g];
        d_Wp2w1[j * G + g] = acc;
    } else if (t < C * G + G) {
        int g = t - C * G;
        float acc = 0.f;
        for (int c = 0; c < C; c++) acc += bp2[c] * Ww1[c * G + g];
        d_bp2w1[g] = acc;
    }
}

// ---------------------------------------------------------------------------
// Kernel 1: point-tiled fused QKV GEMM (scalar FMA).
// 288 threads; thread owns one output column of [Wq|Wk|Wv], 32-point tile,
// acc in registers, feat tile in shared (broadcast LDS.128), weights via L1.
// q,k consumed in-block into qW/kW (never stored globally).
// ---------------------------------------------------------------------------
__global__ __launch_bounds__(288, 3)
void k1_qkv(const float* __restrict__ feat, int n,
            const float* __restrict__ Wq, const float* __restrict__ bq,
            const float* __restrict__ gq, const float* __restrict__ betaq,
            const float* __restrict__ Wk, const float* __restrict__ bk,
            const float* __restrict__ gk, const float* __restrict__ betak,
            const float* __restrict__ Wv, const float* __restrict__ bv,
            const float* __restrict__ Ww1) {
    int base = blockIdx.x * TP;
    int t = threadIdx.x;

    __shared__ __align__(16) float fsh[TP][C];     // 12 KB
    __shared__ float qk[2][TP][QKP];               // 25.6 KB

    for (int e = t; e < TP * C; e += 288) {
        int p = e / C, c = e % C;
        int row = base + p; if (row >= n) row = n - 1;
        fsh[p][c] = feat[row * C + c];
    }
    __syncthreads();

    int m  = t / C;        // 0=q, 1=k, 2=v
    int cc = t % C;
    const float* Wm = (m == 0) ? Wq : (m == 1) ? Wk : Wv;

    float acc[TP];
    #pragma unroll
    for (int p = 0; p < TP; p++) acc[p] = 0.f;

    for (int i0 = 0; i0 < C; i0 += 8) {
        float w[8];
        #pragma unroll
        for (int j = 0; j < 8; j++) w[j] = Wm[(i0 + j) * C + cc];
        #pragma unroll 8
        for (int p = 0; p < TP; p++) {
            float4 f0 = *(const float4*)&fsh[p][i0];
            float4 f1 = *(const float4*)&fsh[p][i0 + 4];
            float a = acc[p];
            a = fmaf(f0.x, w[0], a); a = fmaf(f0.y, w[1], a);
            a = fmaf(f0.z, w[2], a); a = fmaf(f0.w, w[3], a);
            a = fmaf(f1.x, w[4], a); a = fmaf(f1.y, w[5], a);
            a = fmaf(f1.z, w[6], a); a = fmaf(f1.w, w[7], a);
            acc[p] = a;
        }
    }

    if (m == 2) {
        float bias = bv[cc];
        #pragma unroll 8
        for (int p = 0; p < TP; p++) {
            int row = base + p;
            if (row < n) d_v[row * C + cc] = acc[p] + bias;
        }
    } else {
        float bb = (m == 0) ? bq[cc] : bk[cc];
        float sc = bn_scale((m == 0) ? gq[cc] : gk[cc]);
        float be = (m == 0) ? betaq[cc] : betak[cc];
        #pragma unroll 8
        for (int p = 0; p < TP; p++)
            qk[m][p][cc] = fmaxf(fmaf(acc[p] + bb, sc, be), 0.f);
    }
    __syncthreads();

    for (int e = t; e < 2 * TP * G; e += 288) {
        int mm  = e / (TP * G);
        int rem = e % (TP * G);
        int p = rem / G, g = rem % G;
        float a = 0.f;
        #pragma unroll 8
        for (int i = 0; i < C; i += 4) {
            float4 qv = *(const float4*)&qk[mm][p][i];
            a = fmaf(qv.x, Ww1[(i    ) * G + g], a);
            a = fmaf(qv.y, Ww1[(i + 1) * G + g], a);
            a = fmaf(qv.z, Ww1[(i + 2) * G + g], a);
            a = fmaf(qv.w, Ww1[(i + 3) * G + g], a);
        }
        int row = base + p;
        if (row < n) {
            if (mm == 0) d_qW[row * G + g] = a;
            else         d_kW[row * G + g] = a;
        }
    }
}

// ---------------------------------------------------------------------------
// Kernel 2: attention + aggregation. P=4 points per block, 256 threads.
// All phases scalar FMA; staged constants in shared; Hg[P][G][CP] layout so
// phase-8 reads are warp-broadcast (conflict-free).
// ---------------------------------------------------------------------------
__global__ __launch_bounds__(256, 4)
void k2_main(const float* __restrict__ coord,
             const int*   __restrict__ ref, int n,
             const float* __restrict__ Wp1, const float* __restrict__ bp1,
             const float* __restrict__ gp,  const float* __restrict__ betap,
             const float* __restrict__ Wp2, const float* __restrict__ bp2,
             const float* __restrict__ bw1, const float* __restrict__ gw,
             const float* __restrict__ betaw,
             const float* __restrict__ Ww2, const float* __restrict__ bw2,
             float* __restrict__ out) {
    int nb = blockIdx.x * P;
    int t  = threadIdx.x;

    __shared__ float hsh[P][S][CP];    // 24.8 KB  relu(bn(pos@Wp1))
    __shared__ float Hg [P][G][CP];    //  9.3 KB  sum_s w*h
    __shared__ float Wsh[C * G];       //  2.3 KB  folded Wp2@Ww1
    __shared__ float sWp1[3][C];
    __shared__ float sA[C], sB[C];     // bn affine for pos-MLP layer1
    __shared__ float sWw2[G * G];
    __shared__ float sGw[G], sBw[G];   // bn affine for weight-enc layer1
    __shared__ float sBw2[G], sBw1c[G];
    __shared__ float pos[P][S][3];
    __shared__ int   idxsh[P][S];
    __shared__ float msk[P][S];
    __shared__ float kWsh[P][S][G];
    __shared__ float Ash [P][S][G];
    __shared__ float wsh [P][S][G];
    __shared__ float wsum[P][G];
    __shared__ float qWsh[P][G];
    __shared__ float c0[P][3];

    // ---- phase 1: indices + constant staging
    if (t < P * S) {
        int p = t / S, s = t % S;
        int row = nb + p; if (row >= n) row = n - 1;
        int id = ref[row * S + s];
        idxsh[p][s] = id;
        int ip1 = id + 1;
        msk[p][s] = (float)((ip1 > 0) - (ip1 < 0));
    }
    if (t >= 64 && t < 64 + P * 3) {
        int e = t - 64, p = e / 3, d = e % 3;
        int row = nb + p; if (row >= n) row = n - 1;
        c0[p][d] = coord[row * 3 + d];
    }
    if (t >= 96 && t < 96 + P * G) {
        int e = t - 96, p = e / G, g = e % G;
        int row = nb + p; if (row >= n) row = n - 1;
        qWsh[p][g] = d_qW[row * G + g];
    }
    if (t >= 128 && t < 128 + G) {
        int g = t - 128;
        sGw[g]   = bn_scale(gw[g]);
        sBw[g]   = betaw[g];
        sBw2[g]  = bw2[g];
        sBw1c[g] = d_bp2w1[g] + bw1[g];
    }
    if (t >= 160 && t < 160 + G * G) {
        int e = t - 160;
        sWw2[e] = Ww2[e];
    }
    for (int e = t; e < C * G; e += 256) Wsh[e] = d_Wp2w1[e];
    if (t < C) {
        float sc = bn_scale(gp[t]);
        sA[t] = sc;
        sB[t] = fmaf(bp1[t], sc, betap[t]);
        sWp1[0][t] = Wp1[0 * C + t];
        sWp1[1][t] = Wp1[1 * C + t];
        sWp1[2][t] = Wp1[2 * C + t];
    }
    __syncthreads();

    // ---- phase 2: pos + kW gathers
    if (t < P * S * 3) {
        int p = t / (S * 3), rem = t % (S * 3), s = rem / 3, d = rem % 3;
        pos[p][s][d] = coord[idxsh[p][s] * 3 + d] - c0[p][d];
    }
    for (int e = t; e < P * S * G; e += 256) {
        int p = e / (S * G), rem = e % (S * G), s = rem / G, g = rem % G;
        kWsh[p][s][g] = d_kW[idxsh[p][s] * G + g];
    }
    __syncthreads();

    // ---- phase 3: h = relu(bn(pos@Wp1))
    for (int e = t; e < P * S * C; e += 256) {
        int p = e / (S * C), rem = e % (S * C), s = rem / C, c = rem % C;
        float a = fmaf(pos[p][s][0], sWp1[0][c],
                  fmaf(pos[p][s][1], sWp1[1][c],
                       pos[p][s][2] * sWp1[2][c]));
        hsh[p][s][c] = fmaxf(fmaf(a, sA[c], sB[c]), 0.f);
    }
    __syncthreads();

    // ---- phase 4: relation@Ww1 (folded) -> bn -> relu  (scalar)
    for (int e = t; e < P * S * G; e += 256) {
        int p = e / (S * G), rem = e % (S * G), s = rem / G, g = rem % G;
        float u = kWsh[p][s][g] - qWsh[p][g] + sBw1c[g];
        const float* hrow = hsh[p][s];
        #pragma unroll 8
        for (int j = 0; j < C; j++) u = fmaf(hrow[j], Wsh[j * G + g], u);
        Ash[p][s][g] = fmaxf(fmaf(u, sGw[g], sBw[g]), 0.f);
    }
    __syncthreads();

    // ---- phase 5: logits = A @ Ww2 + bw2  (scalar)
    for (int e = t; e < P * S * G; e += 256) {
        int p = e / (S * G), rem = e % (S * G), s = rem / G, g2 = rem % G;
        float l = sBw2[g2];
        #pragma unroll
        for (int g = 0; g < G; g++) l = fmaf(Ash[p][s][g], sWw2[g * G + g2], l);
        wsh[p][s][g2] = l;
    }
    __syncthreads();

    // ---- phase 6: softmax over neighbours + mask
    if (t < P * G) {
        int p = t / G, g = t % G;
        float m = -1e30f;
        #pragma unroll
        for (int s = 0; s < S; s++) m = fmaxf(m, wsh[p][s][g]);
        float sum = 0.f;
        #pragma unroll
        for (int s = 0; s < S; s++) { float e = __expf(wsh[p][s][g] - m); wsh[p][s][g] = e; sum += e; }
        float inv = 1.0f / sum;
        float ws = 0.f;
        #pragma unroll
        for (int s = 0; s < S; s++) {
            float wv = wsh[p][s][g] * inv * msk[p][s];
            wsh[p][s][g] = wv; ws += wv;
        }
        wsum[p][g] = ws;
    }
    __syncthreads();

    // ---- phase 7: Hg[p][g][j] = sum_s w[p,s,g]*h[p,s,j]
    for (int e = t; e < P * G * C; e += 256) {
        int p = e / (G * C), rem = e % (G * C), j = rem / G, g = rem % G;
        float acc = 0.f;
        #pragma unroll
        for (int s = 0; s < S; s++) acc = fmaf(wsh[p][s][g], hsh[p][s][j], acc);
        Hg[p][g][j] = acc;
    }
    __syncthreads();

    // ---- phase 8: out = v-term + Hg@Wp2 + bp2*wsum
    // 192 threads: thread (pp,c) handles points {2pp, 2pp+1}; Wp2 LDG shared
    // across the pair; Hg reads are warp-broadcast; v-term coalesced LDGs.
    if (t < 2 * C) {
        int pp = t / C, c = t % C;
        int g = c / CG;
        int p0 = pp * 2, p1 = pp * 2 + 1;
        float a0 = bp2[c] * wsum[p0][g];
        float a1 = bp2[c] * wsum[p1][g];
        #pragma unroll 8
        for (int j = 0; j < C; j++) {
            float w2 = Wp2[j * C + c];
            a0 = fmaf(Hg[p0][g][j], w2, a0);
            a1 = fmaf(Hg[p1][g][j], w2, a1);
        }
        #pragma unroll
        for (int s = 0; s < S; s++) {
            a0 = fmaf(wsh[p0][s][g], d_v[idxsh[p0][s] * C + c], a0);
            a1 = fmaf(wsh[p1][s][g], d_v[idxsh[p1][s] * C + c], a1);
        }
        int r0 = nb + p0, r1 = nb + p1;
        if (r0 < n) out[r0 * C + c] = a0;
        if (r1 < n) out[r1 * C + c] = a1;
    }
}

// ---------------------------------------------------------------------------
extern "C" void kernel_launch(void* const* d_in, const int* in_sizes, int n_in,
                              void* d_out, int out_size) {
    const float* feat   = (const float*)d_in[0];
    const float* coord  = (const float*)d_in[1];
    const int*   refidx = (const int*)  d_in[2];
    const float* Wq = (const float*)d_in[3];  const float* bq = (const float*)d_in[4];
    const float* gq = (const float*)d_in[5];  const float* betaq = (const float*)d_in[6];
    const float* Wk = (const float*)d_in[7];  const float* bk = (const float*)d_in[8];
    const float* gk = (const float*)d_in[9];  const float* betak = (const float*)d_in[10];
    const float* Wv = (const float*)d_in[11]; const float* bv = (const float*)d_in[12];
    const float* Wp1 = (const float*)d_in[13]; const float* bp1 = (const float*)d_in[14];
    const float* gp  = (const float*)d_in[15]; const float* betap = (const float*)d_in[16];
    const float* Wp2 = (const float*)d_in[17]; const float* bp2 = (const float*)d_in[18];
    const float* Ww1 = (const float*)d_in[19]; const float* bw1 = (const float*)d_in[20];
    const float* gw  = (const float*)d_in[21]; const float* betaw = (const float*)d_in[22];
    const float* Ww2 = (const float*)d_in[23]; const float* bw2 = (const float*)d_in[24];
    float* out = (float*)d_out;

    int n = in_sizes[0] / C;   // 50000

    k0_fold<<<6, 128>>>(Wp2, bp2, Ww1);
    k1_qkv<<<(n + TP - 1) / TP, 288>>>(feat, n, Wq, bq, gq, betaq,
                                       Wk, bk, gk, betak, Wv, bv, Ww1);
    k2_main<<<(n + P - 1) / P, 256>>>(coord, refidx, n, Wp1, bp1, gp, betap,
                                      Wp2, bp2, bw1, gw, betaw, Ww2, bw2, out);
}

// round 9
// speedup vs baseline: 1.1967x; 1.1967x over previous
#include <cuda_runtime.h>
#include <math.h>

#define NPTS 50000
#define S    16
#define C    96
#define CP   97    // padded row: bank-conflict-free [s][*] access
#define G    6
#define CG   16    // C / G
#define TP   32    // points per block in k1
#define TPP  36    // padded point dim in transposed feat tile
#define QKP  100   // padded q/k tile row in k1
#define P    4     // points per block in k2

// ---- scratch (no allocations allowed; __device__ globals are the sanctioned path)
__device__ float d_v [NPTS * C];   // v = feat@Wv + bv
__device__ float d_qW[NPTS * G];   // q @ Ww1
__device__ float d_kW[NPTS * G];   // k @ Ww1
__device__ float d_Wp2w1[C * G];   // Wp2 @ Ww1 (folded)
__device__ float d_bp2w1[G];       // bp2 @ Ww1 (folded)

__device__ __forceinline__ float bn_scale(float g) {
    return g * rsqrtf(1.0f + 1e-5f);
}
__device__ __forceinline__ unsigned long long pack2(float lo, float hi) {
    unsigned long long r;
    asm("mov.b64 %0, {%1, %2};" : "=l"(r) : "r"(__float_as_uint(lo)), "r"(__float_as_uint(hi)));
    return r;
}
__device__ __forceinline__ unsigned long long bcast2(float v) {
    unsigned long long r;
    asm("mov.b64 %0, {%1, %1};" : "=l"(r) : "r"(__float_as_uint(v)));
    return r;
}
__device__ __forceinline__ void unpack2(unsigned long long v, float& lo, float& hi) {
    unsigned l, h;
    asm("mov.b64 {%0, %1}, %2;" : "=r"(l), "=r"(h) : "l"(v));
    lo = __uint_as_float(l); hi = __uint_as_float(h);
}
#define FMA2(acc, a, b) asm("fma.rn.f32x2 %0, %1, %2, %0;" : "+l"(acc) : "l"(a), "l"(b))

// ---------------------------------------------------------------------------
// Kernel 1: block 0 folds Wp2@Ww1 / bp2@Ww1; blocks 1.. run the point-tiled
// fused QKV GEMM with packed f32x2 FMA (feat tile channel-major, point-pairs
// as b64; weight broadcast-packed once per channel).
// Making this the FIRST kernel of each replay also means ncu (-c 1) profiles
// it instead of the trivial fold kernel.
// ---------------------------------------------------------------------------
__global__ __launch_bounds__(288)
void k1_qkv(const float* __restrict__ feat, int n,
            const float* __restrict__ Wq, const float* __restrict__ bq,
            const float* __restrict__ gq, const float* __restrict__ betaq,
            const float* __restrict__ Wk, const float* __restrict__ bk,
            const float* __restrict__ gk, const float* __restrict__ betak,
            const float* __restrict__ Wv, const float* __restrict__ bv,
            const float* __restrict__ Ww1,
            const float* __restrict__ Wp2, const float* __restrict__ bp2) {
    int t = threadIdx.x;

    if (blockIdx.x == 0) {
        // ---- fold block: d_Wp2w1 = Wp2@Ww1, d_bp2w1 = bp2@Ww1
        for (int e = t; e < C * G + G; e += 288) {
            if (e < C * G) {
                int j = e / G, g = e % G;
                float acc = 0.f;
                #pragma unroll 8
                for (int c = 0; c < C; c++) acc += Wp2[j * C + c] * Ww1[c * G + g];
                d_Wp2w1[j * G + g] = acc;
            } else {
                int g = e - C * G;
                float acc = 0.f;
                for (int c = 0; c < C; c++) acc += bp2[c] * Ww1[c * G + g];
                d_bp2w1[g] = acc;
            }
        }
        return;
    }

    int base = (blockIdx.x - 1) * TP;

    __shared__ __align__(16) float fsh2[C][TPP];   // 13.8 KB transposed feat
    __shared__ float qk[2][TP][QKP];               // 25.6 KB post-bn-relu q,k

    for (int e = t; e < TP * C; e += 288) {
        int p = e / C, c = e % C;
        int row = base + p; if (row >= n) row = n - 1;
        fsh2[c][p] = feat[row * C + c];
    }
    __syncthreads();

    int m  = t / C;        // 0=q, 1=k, 2=v
    int cc = t % C;
    const float* Wm = (m == 0) ? Wq : (m == 1) ? Wk : Wv;

    unsigned long long acc2[TP / 2];
    #pragma unroll
    for (int pp = 0; pp < TP / 2; pp++) acc2[pp] = 0ull;

    #pragma unroll 4
    for (int i = 0; i < C; i++) {
        unsigned long long w2 = bcast2(Wm[i * C + cc]);
        const ulonglong2* frow = (const ulonglong2*)&fsh2[i][0];
        #pragma unroll
        for (int q4 = 0; q4 < TP / 4; q4++) {
            ulonglong2 f = frow[q4];   // LDS.128: 4 points, channel i (broadcast)
            FMA2(acc2[q4 * 2    ], f.x, w2);
            FMA2(acc2[q4 * 2 + 1], f.y, w2);
        }
    }

    if (m == 2) {
        float bias = bv[cc];
        #pragma unroll
        for (int pp = 0; pp < TP / 2; pp++) {
            float lo, hi; unpack2(acc2[pp], lo, hi);
            int r0 = base + 2 * pp, r1 = r0 + 1;
            if (r0 < n) d_v[r0 * C + cc] = lo + bias;
            if (r1 < n) d_v[r1 * C + cc] = hi + bias;
        }
    } else {
        float bb = (m == 0) ? bq[cc] : bk[cc];
        float sc = bn_scale((m == 0) ? gq[cc] : gk[cc]);
        float be = (m == 0) ? betaq[cc] : betak[cc];
        #pragma unroll
        for (int pp = 0; pp < TP / 2; pp++) {
            float lo, hi; unpack2(acc2[pp], lo, hi);
            qk[m][2 * pp    ][cc] = fmaxf(fmaf(lo + bb, sc, be), 0.f);
            qk[m][2 * pp + 1][cc] = fmaxf(fmaf(hi + bb, sc, be), 0.f);
        }
    }
    __syncthreads();

    for (int e = t; e < 2 * TP * G; e += 288) {
        int mm  = e / (TP * G);
        int rem = e % (TP * G);
        int p = rem / G, g = rem % G;
        float a = 0.f;
        #pragma unroll 8
        for (int i = 0; i < C; i += 4) {
            float4 qv = *(const float4*)&qk[mm][p][i];
            a = fmaf(qv.x, Ww1[(i    ) * G + g], a);
            a = fmaf(qv.y, Ww1[(i + 1) * G + g], a);
            a = fmaf(qv.z, Ww1[(i + 2) * G + g], a);
            a = fmaf(qv.w, Ww1[(i + 3) * G + g], a);
        }
        int row = base + p;
        if (row < n) {
            if (mm == 0) d_qW[row * G + g] = a;
            else         d_kW[row * G + g] = a;
        }
    }
}

// ---------------------------------------------------------------------------
// Kernel 2: attention + aggregation. P=4 points per block, 256 threads.
// Packed f32x2 in phases 4, 5 (g-pairs) and 8 (point-pairs via Hg[G][C][P]).
// ---------------------------------------------------------------------------
__global__ __launch_bounds__(256)
void k2_main(const float* __restrict__ coord,
             const int*   __restrict__ ref, int n,
             const float* __restrict__ Wp1, const float* __restrict__ bp1,
             const float* __restrict__ gp,  const float* __restrict__ betap,
             const float* __restrict__ Wp2, const float* __restrict__ bp2,
             const float* __restrict__ bw1, const float* __restrict__ gw,
             const float* __restrict__ betaw,
             const float* __restrict__ Ww2, const float* __restrict__ bw2,
             float* __restrict__ out) {
    int nb = blockIdx.x * P;
    int t  = threadIdx.x;

    __shared__ float hsh[P][S][CP];              // 24.8 KB  relu(bn(pos@Wp1))
    __shared__ __align__(16) float Hg[G * C * P];//  9.2 KB  [g][j][p] point-major
    __shared__ __align__(16) float Wsh[C * G];   //  2.3 KB  folded Wp2@Ww1
    __shared__ float sWp1[3][C];
    __shared__ float sA[C], sB[C];               // bn affine for pos-MLP layer1
    __shared__ __align__(8) float sWw2[G * G];
    __shared__ float sGw[G], sBw[G];             // bn affine for weight-enc layer1
    __shared__ float sBw2[G], sBw1c[G];          // bw2; bw1+bp2w1 combined
    __shared__ float pos[P][S][3];
    __shared__ int   idxsh[P][S];
    __shared__ float msk[P][S];
    __shared__ float kWsh[P][S][G];
    __shared__ float Ash [P][S][G];
    __shared__ float wsh [P][S][G];
    __shared__ float wsum[P][G];
    __shared__ float qWsh[P][G];
    __shared__ float c0[P][3];

    // ---- phase 1: indices + constant staging
    if (t < P * S) {
        int p = t / S, s = t % S;
        int row = nb + p; if (row >= n) row = n - 1;
        int id = ref[row * S + s];
        idxsh[p][s] = id;
        int ip1 = id + 1;
        msk[p][s] = (float)((ip1 > 0) - (ip1 < 0));
    }
    if (t >= 64 && t < 64 + P * 3) {
        int e = t - 64, p = e / 3, d = e % 3;
        int row = nb + p; if (row >= n) row = n - 1;
        c0[p][d] = coord[row * 3 + d];
    }
    if (t >= 96 && t < 96 + P * G) {
        int e = t - 96, p = e / G, g = e % G;
        int row = nb + p; if (row >= n) row = n - 1;
        qWsh[p][g] = d_qW[row * G + g];
    }
    if (t >= 128 && t < 128 + G) {
        int g = t - 128;
        sGw[g]   = bn_scale(gw[g]);
        sBw[g]   = betaw[g];
        sBw2[g]  = bw2[g];
        sBw1c[g] = d_bp2w1[g] + bw1[g];
    }
    if (t >= 160 && t < 160 + G * G) {
        int e = t - 160;
        sWw2[e] = Ww2[e];
    }
    for (int e = t; e < C * G; e += 256) Wsh[e] = d_Wp2w1[e];
    if (t < C) {
        float sc = bn_scale(gp[t]);
        sA[t] = sc;
        sB[t] = fmaf(bp1[t], sc, betap[t]);
        sWp1[0][t] = Wp1[0 * C + t];
        sWp1[1][t] = Wp1[1 * C + t];
        sWp1[2][t] = Wp1[2 * C + t];
    }
    __syncthreads();

    // ---- phase 2: pos + kW gathers
    if (t < P * S * 3) {
        int p = t / (S * 3), rem = t % (S * 3), s = rem / 3, d = rem % 3;
        pos[p][s][d] = coord[idxsh[p][s] * 3 + d] - c0[p][d];
    }
    for (int e = t; e < P * S * G; e += 256) {
        int p = e / (S * G), rem = e % (S * G), s = rem / G, g = rem % G;
        kWsh[p][s][g] = d_kW[idxsh[p][s] * G + g];
    }
    __syncthreads();

    // ---- phase 3: h = relu(bn(pos@Wp1))
    for (int e = t; e < P * S * C; e += 256) {
        int p = e / (S * C), rem = e % (S * C), s = rem / C, c = rem % C;
        float a = fmaf(pos[p][s][0], sWp1[0][c],
                  fmaf(pos[p][s][1], sWp1[1][c],
                       pos[p][s][2] * sWp1[2][c]));
        hsh[p][s][c] = fmaxf(fmaf(a, sA[c], sB[c]), 0.f);
    }
    __syncthreads();

    // ---- phase 4: relation@Ww1 (folded) -> bn -> relu, g-pairs packed
    if (t < P * S * (G / 2)) {       // 192 threads, single shot
        int p = t / (S * 3), rem = t % (S * 3), s = rem / 3, gp2 = rem % 3;
        int g0 = gp2 * 2, g1 = g0 + 1;
        unsigned long long u2 = pack2(
            kWsh[p][s][g0] - qWsh[p][g0] + sBw1c[g0],
            kWsh[p][s][g1] - qWsh[p][g1] + sBw1c[g1]);
        const float* hrow = hsh[p][s];
        #pragma unroll 8
        for (int j = 0; j < C; j++) {
            unsigned long long h2 = bcast2(hrow[j]);
            unsigned long long w2 = *(const unsigned long long*)&Wsh[j * G + g0]; // 8B-aligned
            FMA2(u2, h2, w2);
        }
        float u0, u1; unpack2(u2, u0, u1);
        Ash[p][s][g0] = fmaxf(fmaf(u0, sGw[g0], sBw[g0]), 0.f);
        Ash[p][s][g1] = fmaxf(fmaf(u1, sGw[g1], sBw[g1]), 0.f);
    }
    __syncthreads();

    // ---- phase 5: logits = A @ Ww2 + bw2, g2-pairs packed
    if (t < P * S * (G / 2)) {       // 192 threads, single shot
        int p = t / (S * 3), rem = t % (S * 3), s = rem / 3, gp2 = rem % 3;
        int g0 = gp2 * 2, g1 = g0 + 1;
        unsigned long long l2 = pack2(sBw2[g0], sBw2[g1]);
        const float* arow = Ash[p][s];
        #pragma unroll
        for (int g = 0; g < G; g++) {
            unsigned long long a2 = bcast2(arow[g]);
            unsigned long long w2 = *(const unsigned long long*)&sWw2[g * G + g0]; // 8B-aligned
            FMA2(l2, a2, w2);
        }
        float l0, l1; unpack2(l2, l0, l1);
        wsh[p][s][g0] = l0;
        wsh[p][s][g1] = l1;
    }
    __syncthreads();

    // ---- phase 6: softmax over neighbours + mask
    if (t < P * G) {
        int p = t / G, g = t % G;
        float m = -1e30f;
        #pragma unroll
        for (int s = 0; s < S; s++) m = fmaxf(m, wsh[p][s][g]);
        float sum = 0.f;
        #pragma unroll
        for (int s = 0; s < S; s++) { float e = __expf(wsh[p][s][g] - m); wsh[p][s][g] = e; sum += e; }
        float inv = 1.0f / sum;
        float ws = 0.f;
        #pragma unroll
        for (int s = 0; s < S; s++) {
            float wv = wsh[p][s][g] * inv * msk[p][s];
            wsh[p][s][g] = wv; ws += wv;
        }
        wsum[p][g] = ws;
    }
    __syncthreads();

    // ---- phase 7: Hg[g][j][p] = sum_s w[p,s,g]*h[p,s,j]  (point-major layout)
    for (int e = t; e < G * C; e += 256) {
        int g = e / C, j = e % C;
        float4 acc = make_float4(0.f, 0.f, 0.f, 0.f);
        #pragma unroll
        for (int s = 0; s < S; s++) {
            acc.x = fmaf(wsh[0][s][g], hsh[0][s][j], acc.x);
            acc.y = fmaf(wsh[1][s][g], hsh[1][s][j], acc.y);
            acc.z = fmaf(wsh[2][s][g], hsh[2][s][j], acc.z);
            acc.w = fmaf(wsh[3][s][g], hsh[3][s][j], acc.w);
        }
        *(float4*)&Hg[(g * C + j) * P] = acc;   // STS.128
    }
    __syncthreads();

    // ---- phase 8: out = v-term + Hg@Wp2 + bp2*wsum, point-pairs packed
    if (t < 2 * C) {
        int pp = t / C, c = t % C;
        int g = c / CG;
        int p0 = pp * 2, p1 = pp * 2 + 1;
        unsigned long long a2 = pack2(bp2[c] * wsum[p0][g], bp2[c] * wsum[p1][g]);
        #pragma unroll 8
        for (int j = 0; j < C; j++) {
            unsigned long long w2 = bcast2(Wp2[j * C + c]);
            unsigned long long h2 = *(const unsigned long long*)&Hg[(g * C + j) * P + p0]; // 8B-aligned
            FMA2(a2, h2, w2);
        }
        float a0, a1; unpack2(a2, a0, a1);
        #pragma unroll
        for (int s = 0; s < S; s++) {
            a0 = fmaf(wsh[p0][s][g], d_v[idxsh[p0][s] * C + c], a0);
            a1 = fmaf(wsh[p1][s][g], d_v[idxsh[p1][s] * C + c], a1);
        }
        int r0 = nb + p0, r1 = nb + p1;
        if (r0 < n) out[r0 * C + c] = a0;
        if (r1 < n) out[r1 * C + c] = a1;
    }
}

// ---------------------------------------------------------------------------
extern "C" void kernel_launch(void* const* d_in, const int* in_sizes, int n_in,
                              void* d_out, int out_size) {
    const float* feat   = (const float*)d_in[0];
    const float* coord  = (const float*)d_in[1];
    const int*   refidx = (const int*)  d_in[2];
    const float* Wq = (const float*)d_in[3];  const float* bq = (const float*)d_in[4];
    const float* gq = (const float*)d_in[5];  const float* betaq = (const float*)d_in[6];
    const float* Wk = (const float*)d_in[7];  const float* bk = (const float*)d_in[8];
    const float* gk = (const float*)d_in[9];  const float* betak = (const float*)d_in[10];
    const float* Wv = (const float*)d_in[11]; const float* bv = (const float*)d_in[12];
    const float* Wp1 = (const float*)d_in[13]; const float* bp1 = (const float*)d_in[14];
    const float* gp  = (const float*)d_in[15]; const float* betap = (const float*)d_in[16];
    const float* Wp2 = (const float*)d_in[17]; const float* bp2 = (const float*)d_in[18];
    const float* Ww1 = (const float*)d_in[19]; const float* bw1 = (const float*)d_in[20];
    const float* gw  = (const float*)d_in[21]; const float* betaw = (const float*)d_in[22];
    const float* Ww2 = (const float*)d_in[23]; const float* bw2 = (const float*)d_in[24];
    float* out = (float*)d_out;

    int n = in_sizes[0] / C;   // 50000

    k1_qkv<<<1 + (n + TP - 1) / TP, 288>>>(feat, n, Wq, bq, gq, betaq,
                                           Wk, bk, gk, betak, Wv, bv, Ww1,
                                           Wp2, bp2);
    k2_main<<<(n + P - 1) / P, 256>>>(coord, refidx, n, Wp1, bp1, gp, betap,
                                      Wp2, bp2, bw1, gw, betaw, Ww2, bw2, out);
}

// round 13
// speedup vs baseline: 1.6477x; 1.3769x over previous
#include <cuda_runtime.h>
#include <math.h>

#define NPTS 50000
#define S    16
#define C    96
#define CP   97    // padded hsh row (conflict-free: 97 % 32 == 1)
#define G    6
#define CG   16
#define TP   32    // points per block in k1
#define TPP  36
#define QKP  100
#define P    4     // points per block in k2
#define HGS  (C*4 + 4)   // Hg per-g stride in floats (pad 4 -> bank offset per g)

// ---- scratch
__device__ float d_v [NPTS * C];
__device__ float d_qW[NPTS * G];
__device__ float d_kW[NPTS * G];
__device__ float d_Wp2w1[C * G];
__device__ float d_bp2w1[G];

__device__ __forceinline__ float bn_scale(float g) {
    return g * rsqrtf(1.0f + 1e-5f);
}
__device__ __forceinline__ unsigned long long pack2(float lo, float hi) {
    unsigned long long r;
    asm("mov.b64 %0, {%1, %2};" : "=l"(r) : "r"(__float_as_uint(lo)), "r"(__float_as_uint(hi)));
    return r;
}
__device__ __forceinline__ unsigned long long bcast2(float v) {
    unsigned long long r;
    asm("mov.b64 %0, {%1, %1};" : "=l"(r) : "r"(__float_as_uint(v)));
    return r;
}
__device__ __forceinline__ void unpack2(unsigned long long v, float& lo, float& hi) {
    unsigned l, h;
    asm("mov.b64 {%0, %1}, %2;" : "=r"(l), "=r"(h) : "l"(v));
    lo = __uint_as_float(l); hi = __uint_as_float(h);
}
#define FMA2(acc, a, b) asm("fma.rn.f32x2 %0, %1, %2, %0;" : "+l"(acc) : "l"(a), "l"(b))

// ---------------------------------------------------------------------------
// Kernel 1: block 0 folds Wp2@Ww1; blocks 1.. packed-f32x2 fused QKV GEMM.
// (unchanged from the 509us measured config)
// ---------------------------------------------------------------------------
__global__ __launch_bounds__(288)
void k1_qkv(const float* __restrict__ feat, int n,
            const float* __restrict__ Wq, const float* __restrict__ bq,
            const float* __restrict__ gq, const float* __restrict__ betaq,
            const float* __restrict__ Wk, const float* __restrict__ bk,
            const float* __restrict__ gk, const float* __restrict__ betak,
            const float* __restrict__ Wv, const float* __restrict__ bv,
            const float* __restrict__ Ww1,
            const float* __restrict__ Wp2, const float* __restrict__ bp2) {
    int t = threadIdx.x;

    if (blockIdx.x == 0) {
        for (int e = t; e < C * G + G; e += 288) {
            if (e < C * G) {
                int j = e / G, g = e % G;
                float acc = 0.f;
                #pragma unroll 8
                for (int c = 0; c < C; c++) acc += Wp2[j * C + c] * Ww1[c * G + g];
                d_Wp2w1[j * G + g] = acc;
            } else {
                int g = e - C * G;
                float acc = 0.f;
                for (int c = 0; c < C; c++) acc += bp2[c] * Ww1[c * G + g];
                d_bp2w1[g] = acc;
            }
        }
        return;
    }

    int base = (blockIdx.x - 1) * TP;

    __shared__ __align__(16) float fsh2[C][TPP];
    __shared__ float qk[2][TP][QKP];

    for (int e = t; e < TP * C; e += 288) {
        int p = e / C, c = e % C;
        int row = base + p; if (row >= n) row = n - 1;
        fsh2[c][p] = feat[row * C + c];
    }
    __syncthreads();

    int m  = t / C;
    int cc = t % C;
    const float* Wm = (m == 0) ? Wq : (m == 1) ? Wk : Wv;

    unsigned long long acc2[TP / 2];
    #pragma unroll
    for (int pp = 0; pp < TP / 2; pp++) acc2[pp] = 0ull;

    #pragma unroll 4
    for (int i = 0; i < C; i++) {
        unsigned long long w2 = bcast2(Wm[i * C + cc]);
        const ulonglong2* frow = (const ulonglong2*)&fsh2[i][0];
        #pragma unroll
        for (int q4 = 0; q4 < TP / 4; q4++) {
            ulonglong2 f = frow[q4];
            FMA2(acc2[q4 * 2    ], f.x, w2);
            FMA2(acc2[q4 * 2 + 1], f.y, w2);
        }
    }

    if (m == 2) {
        float bias = bv[cc];
        #pragma unroll
        for (int pp = 0; pp < TP / 2; pp++) {
            float lo, hi; unpack2(acc2[pp], lo, hi);
            int r0 = base + 2 * pp, r1 = r0 + 1;
            if (r0 < n) d_v[r0 * C + cc] = lo + bias;
            if (r1 < n) d_v[r1 * C + cc] = hi + bias;
        }
    } else {
        float bb = (m == 0) ? bq[cc] : bk[cc];
        float sc = bn_scale((m == 0) ? gq[cc] : gk[cc]);
        float be = (m == 0) ? betaq[cc] : betak[cc];
        #pragma unroll
        for (int pp = 0; pp < TP / 2; pp++) {
            float lo, hi; unpack2(acc2[pp], lo, hi);
            qk[m][2 * pp    ][cc] = fmaxf(fmaf(lo + bb, sc, be), 0.f);
            qk[m][2 * pp + 1][cc] = fmaxf(fmaf(hi + bb, sc, be), 0.f);
        }
    }
    __syncthreads();

    for (int e = t; e < 2 * TP * G; e += 288) {
        int mm  = e / (TP * G);
        int rem = e % (TP * G);
        int p = rem / G, g = rem % G;
        float a = 0.f;
        #pragma unroll 8
        for (int i = 0; i < C; i += 4) {
            float4 qv = *(const float4*)&qk[mm][p][i];
            a = fmaf(qv.x, Ww1[(i    ) * G + g], a);
            a = fmaf(qv.y, Ww1[(i + 1) * G + g], a);
            a = fmaf(qv.z, Ww1[(i + 2) * G + g], a);
            a = fmaf(qv.w, Ww1[(i + 3) * G + g], a);
        }
        int row = base + p;
        if (row < n) {
            if (mm == 0) d_qW[row * G + g] = a;
            else         d_kW[row * G + g] = a;
        }
    }
}

// ---------------------------------------------------------------------------
// Kernel 2: restructured for minimal shared-memory wavefronts.
// ---------------------------------------------------------------------------
__global__ __launch_bounds__(256)
void k2_main(const float* __restrict__ coord,
             const int*   __restrict__ ref, int n,
             const float* __restrict__ Wp1, const float* __restrict__ bp1,
             const float* __restrict__ gp,  const float* __restrict__ betap,
             const float* __restrict__ Wp2, const float* __restrict__ bp2,
             const float* __restrict__ bw1, const float* __restrict__ gw,
             const float* __restrict__ betaw,
             const float* __restrict__ Ww2, const float* __restrict__ bw2,
             float* __restrict__ out) {
    int nb = blockIdx.x * P;
    int t  = threadIdx.x;
    int lane = t & 31, wid = t >> 5;

    __shared__ float hsh[P * S * CP];                 // 24.8 KB [ps][97]
    __shared__ __align__(16) float Hg[G * HGS];       //  9.3 KB [g][j][4p], padded
    __shared__ __align__(16) float Wsh8[C * 8];       //  3.0 KB Wp2w1 padded to 8/row
    __shared__ __align__(16) unsigned long long wpack[S * G * 2]; // 1.5 KB packed p-pair weights
    __shared__ __align__(16) float4 pos4sh[P * S];    //  1.0 KB
    __shared__ float sWp1[3 * C];
    __shared__ float sA[C], sB[C];
    __shared__ float sWw2[G * G];
    __shared__ float sGw[G], sBw[G], sBw2[G], sBw1c[G];
    __shared__ int   idxsh[P * S];
    __shared__ float msk[P * S];
    __shared__ float kWsh[P * S * G];
    __shared__ float Ash [P * S * G];
    __shared__ float wsh [P * S * G];
    __shared__ float wsum[P * G];
    __shared__ float qWsh[P * G];
    __shared__ float c0[P][3];

    // ---- phase 1: staging
    if (t < P * S) {
        int p = t >> 4, s = t & 15;
        int row = nb + p; if (row >= n) row = n - 1;
        int id = ref[row * S + s];
        idxsh[t] = id;
        int ip1 = id + 1;
        msk[t] = (float)((ip1 > 0) - (ip1 < 0));
    }
    if (t >= 64 && t < 64 + P * 3) {
        int e = t - 64, p = e / 3, d = e % 3;
        int row = nb + p; if (row >= n) row = n - 1;
        c0[p][d] = coord[row * 3 + d];
    }
    if (t >= 96 && t < 96 + P * G) {
        int e = t - 96, p = e / G, g = e % G;
        int row = nb + p; if (row >= n) row = n - 1;
        qWsh[p * G + g] = d_qW[row * G + g];
    }
    if (t >= 128 && t < 128 + G) {
        int g = t - 128;
        sGw[g]   = bn_scale(gw[g]);
        sBw[g]   = betaw[g];
        sBw2[g]  = bw2[g];
        sBw1c[g] = d_bp2w1[g] + bw1[g];
    }
    if (t >= 160 && t < 160 + G * G) sWw2[t - 160] = Ww2[t - 160];
    #pragma unroll
    for (int e = t; e < C * 8; e += 256) {
        int j = e >> 3, kk = e & 7;
        Wsh8[e] = (kk < G) ? d_Wp2w1[j * G + kk] : 0.f;
    }
    if (t < C) {
        float sc = bn_scale(gp[t]);
        sA[t] = sc;
        sB[t] = fmaf(bp1[t], sc, betap[t]);
        sWp1[0 * C + t] = Wp1[0 * C + t];
        sWp1[1 * C + t] = Wp1[1 * C + t];
        sWp1[2 * C + t] = Wp1[2 * C + t];
    }
    __syncthreads();

    // ---- phase 2: pos (packed float4) + kW gathers
    if (t < P * S) {
        int p = t >> 4;
        int id = idxsh[t];
        float4 v;
        v.x = coord[id * 3 + 0] - c0[p][0];
        v.y = coord[id * 3 + 1] - c0[p][1];
        v.z = coord[id * 3 + 2] - c0[p][2];
        v.w = 0.f;
        pos4sh[t] = v;
    }
    for (int e = t; e < P * S * G; e += 256) {
        int ps = e / G, g = e - (e / G) * G;
        kWsh[ps * G + g] = d_kW[idxsh[ps] * G + g];
    }
    __syncthreads();

    // ---- phase 3: h = relu(bn(pos@Wp1)); c-persistent warps, pos bcast as float4
    if (wid < 6) {
        int chunk = wid >> 1, pp = wid & 1;       // c-chunk 0..2, p-pair 0..1
        int c = chunk * 32 + lane;
        float w0 = sWp1[0 * C + c], w1 = sWp1[1 * C + c], w2 = sWp1[2 * C + c];
        float aa = sA[c], bb = sB[c];
        #pragma unroll 4
        for (int s = 0; s < S; s++) {
            #pragma unroll
            for (int pq = 0; pq < 2; pq++) {
                int p = pp * 2 + pq;
                float4 ps4 = pos4sh[p * S + s];
                float h = fmaf(ps4.x, w0, fmaf(ps4.y, w1, ps4.z * w2));
                hsh[(p * S + s) * CP + c] = fmaxf(fmaf(h, aa, bb), 0.f);
            }
        }
    }
    __syncthreads();

    // ---- phase 4: relation@Ww1 -> bn -> relu. 64 threads = (p,s) lanes:
    // h loads conflict-free (stride 97), W bcast via 2 vector loads/j.
    if (t < P * S) {
        int ps = t, p = t >> 4;
        unsigned long long u2[3];
        #pragma unroll
        for (int gp2 = 0; gp2 < 3; gp2++) {
            int g0 = gp2 * 2, g1 = g0 + 1;
            u2[gp2] = pack2(kWsh[ps * G + g0] - qWsh[p * G + g0] + sBw1c[g0],
                            kWsh[ps * G + g1] - qWsh[p * G + g1] + sBw1c[g1]);
        }
        const float* hrow = &hsh[ps * CP];
        #pragma unroll 4
        for (int j = 0; j < C; j++) {
            unsigned long long h2 = bcast2(hrow[j]);
            ulonglong2 wv = *(const ulonglong2*)&Wsh8[j * 8];       // g0..g3
            unsigned long long w45 = *(const unsigned long long*)&Wsh8[j * 8 + 4];
            FMA2(u2[0], h2, wv.x);
            FMA2(u2[1], h2, wv.y);
            FMA2(u2[2], h2, w45);
        }
        #pragma unroll
        for (int gp2 = 0; gp2 < 3; gp2++) {
            int g0 = gp2 * 2, g1 = g0 + 1;
            float u0, u1; unpack2(u2[gp2], u0, u1);
            Ash[ps * G + g0] = fmaxf(fmaf(u0, sGw[g0], sBw[g0]), 0.f);
            Ash[ps * G + g1] = fmaxf(fmaf(u1, sGw[g1], sBw[g1]), 0.f);
        }
    }
    __syncthreads();

    // ---- phase 5: logits = A @ Ww2 + bw2 (g-pairs packed)
    if (t < P * S * 3) {
        int ps = t / 3, gp2 = t - (t / 3) * 3;
        int g0 = gp2 * 2, g1 = g0 + 1;
        unsigned long long l2 = pack2(sBw2[g0], sBw2[g1]);
        const float* arow = &Ash[ps * G];
        #pragma unroll
        for (int g = 0; g < G; g++) {
            unsigned long long a2 = bcast2(arow[g]);
            unsigned long long w2 = *(const unsigned long long*)&sWw2[g * G + g0];
            FMA2(l2, a2, w2);
        }
        float l0, l1; unpack2(l2, l0, l1);
        wsh[ps * G + g0] = l0;
        wsh[ps * G + g1] = l1;
    }
    __syncthreads();

    // ---- phase 6: softmax over neighbours + mask
    if (t < P * G) {
        int p = t / G, g = t - (t / G) * G;
        float m = -1e30f;
        #pragma unroll
        for (int s = 0; s < S; s++) m = fmaxf(m, wsh[(p * S + s) * G + g]);
        float sum = 0.f;
        #pragma unroll
        for (int s = 0; s < S; s++) {
            float e = __expf(wsh[(p * S + s) * G + g] - m);
            wsh[(p * S + s) * G + g] = e; sum += e;
        }
        float inv = 1.0f / sum;
        float ws = 0.f;
        #pragma unroll
        for (int s = 0; s < S; s++) {
            float wv = wsh[(p * S + s) * G + g] * inv * msk[p * S + s];
            wsh[(p * S + s) * G + g] = wv; ws += wv;
        }
        wsum[p * G + g] = ws;
    }
    __syncthreads();

    // ---- phase 6b: prepack w as p-pairs for phase 7
    if (t < S * G * 2) {
        int s = t / 12, r = t - (t / 12) * 12, g = r >> 1, pp = r & 1;
        wpack[(s * G + g) * 2 + pp] =
            pack2(wsh[((pp * 2    ) * S + s) * G + g],
                  wsh[((pp * 2 + 1) * S + s) * G + g]);
    }
    __syncthreads();

    // ---- phase 7: Hg[g][j][p] = sum_s w[p,s,g]*h[p,s,j]
    // 3 j-window warps; 12 packed accumulators/lane; each h load feeds 6 g.
    if (wid < 3) {
        int j = wid * 32 + lane;
        unsigned long long acc[12];
        #pragma unroll
        for (int i = 0; i < 12; i++) acc[i] = 0ull;
        #pragma unroll 4
        for (int s = 0; s < S; s++) {
            float h0 = hsh[(0 * S + s) * CP + j];
            float h1 = hsh[(1 * S + s) * CP + j];
            float h2v = hsh[(2 * S + s) * CP + j];
            float h3 = hsh[(3 * S + s) * CP + j];
            unsigned long long h01 = pack2(h0, h1);
            unsigned long long h23 = pack2(h2v, h3);
            #pragma unroll
            for (int g = 0; g < G; g++) {
                ulonglong2 wv = *(const ulonglong2*)&wpack[(s * G + g) * 2];
                FMA2(acc[g * 2    ], h01, wv.x);
                FMA2(acc[g * 2 + 1], h23, wv.y);
            }
        }
        #pragma unroll
        for (int g = 0; g < G; g++) {
            float4 o;
            unpack2(acc[g * 2    ], o.x, o.y);
            unpack2(acc[g * 2 + 1], o.z, o.w);
            *(float4*)&Hg[g * HGS + j * 4] = o;
        }
    }
    __syncthreads();

    // ---- phase 8: out = v-term + Hg@Wp2 + bp2*wsum; 96 threads own all 4 p.
    if (t < C) {
        int c = t, g = c >> 4;
        float bp2c = bp2[c];
        unsigned long long a01 = pack2(bp2c * wsum[0 * G + g], bp2c * wsum[1 * G + g]);
        unsigned long long a23 = pack2(bp2c * wsum[2 * G + g], bp2c * wsum[3 * G + g]);
        #pragma unroll 4
        for (int j = 0; j < C; j++) {
            ulonglong2 hg = *(const ulonglong2*)&Hg[g * HGS + j * 4];  // broadcast, conflict-free
            unsigned long long w2 = bcast2(Wp2[j * C + c]);
            FMA2(a01, hg.x, w2);
            FMA2(a23, hg.y, w2);
        }
        float a0, a1, a2, a3;
        unpack2(a01, a0, a1);
        unpack2(a23, a2, a3);
        #pragma unroll 4
        for (int s = 0; s < S; s++) {
            a0 = fmaf(wsh[(0 * S + s) * G + g], d_v[idxsh[0 * S + s] * C + c], a0);
            a1 = fmaf(wsh[(1 * S + s) * G + g], d_v[idxsh[1 * S + s] * C + c], a1);
            a2 = fmaf(wsh[(2 * S + s) * G + g], d_v[idxsh[2 * S + s] * C + c], a2);
            a3 = fmaf(wsh[(3 * S + s) * G + g], d_v[idxsh[3 * S + s] * C + c], a3);
        }
        int r0 = nb, r1 = nb + 1, r2 = nb + 2, r3 = nb + 3;
        if (r0 < n) out[r0 * C + c] = a0;
        if (r1 < n) out[r1 * C + c] = a1;
        if (r2 < n) out[r2 * C + c] = a2;
        if (r3 < n) out[r3 * C + c] = a3;
    }
}

// ---------------------------------------------------------------------------
extern "C" void kernel_launch(void* const* d_in, const int* in_sizes, int n_in,
                              void* d_out, int out_size) {
    const float* feat   = (const float*)d_in[0];
    const float* coord  = (const float*)d_in[1];
    const int*   refidx = (const int*)  d_in[2];
    const float* Wq = (const float*)d_in[3];  const float* bq = (const float*)d_in[4];
    const float* gq = (const float*)d_in[5];  const float* betaq = (const float*)d_in[6];
    const float* Wk = (const float*)d_in[7];  const float* bk = (const float*)d_in[8];
    const float* gk = (const float*)d_in[9];  const float* betak = (const float*)d_in[10];
    const float* Wv = (const float*)d_in[11]; const float* bv = (const float*)d_in[12];
    const float* Wp1 = (const float*)d_in[13]; const float* bp1 = (const float*)d_in[14];
    const float* gp  = (const float*)d_in[15]; const float* betap = (const float*)d_in[16];
    const float* Wp2 = (const float*)d_in[17]; const float* bp2 = (const float*)d_in[18];
    const float* Ww1 = (const float*)d_in[19]; const float* bw1 = (const float*)d_in[20];
    const float* gw  = (const float*)d_in[21]; const float* betaw = (const float*)d_in[22];
    const float* Ww2 = (const float*)d_in[23]; const float* bw2 = (const float*)d_in[24];
    float* out = (float*)d_out;

    int n = in_sizes[0] / C;   // 50000

    k1_qkv<<<1 + (n + TP - 1) / TP, 288>>>(feat, n, Wq, bq, gq, betaq,
                                           Wk, bk, gk, betak, Wv, bv, Ww1,
                                           Wp2, bp2);
    k2_main<<<(n + P - 1) / P, 256>>>(coord, refidx, n, Wp1, bp1, gp, betap,
                                      Wp2, bp2, bw1, gw, betaw, Ww2, bw2, out);
}

// round 15
// speedup vs baseline: 1.6520x; 1.0026x over previous
#include <cuda_runtime.h>
#include <math.h>

#define NPTS 50000
#define S    16
#define C    96
#define CP   97    // padded hsh row (conflict-free: 97 % 32 == 1)
#define G    6
#define CG   16
#define TP   32    // points per block in k1
#define TPP  36
#define QKP  100
#define P    4     // points per block in k2
#define HGS  (C*4 + 4)   // Hg per-g stride in floats (pad 4 -> bank offset per g)

// ---- scratch
__device__ float d_v [NPTS * C];
__device__ float d_qW[NPTS * G];
__device__ float d_kW[NPTS * G];
__device__ float d_Wp2w1[C * G];
__device__ float d_bp2w1[G];

__device__ __forceinline__ float bn_scale(float g) {
    return g * rsqrtf(1.0f + 1e-5f);
}
__device__ __forceinline__ unsigned long long pack2(float lo, float hi) {
    unsigned long long r;
    asm("mov.b64 %0, {%1, %2};" : "=l"(r) : "r"(__float_as_uint(lo)), "r"(__float_as_uint(hi)));
    return r;
}
__device__ __forceinline__ unsigned long long bcast2(float v) {
    unsigned long long r;
    asm("mov.b64 %0, {%1, %1};" : "=l"(r) : "r"(__float_as_uint(v)));
    return r;
}
__device__ __forceinline__ void unpack2(unsigned long long v, float& lo, float& hi) {
    unsigned l, h;
    asm("mov.b64 {%0, %1}, %2;" : "=r"(l), "=r"(h) : "l"(v));
    lo = __uint_as_float(l); hi = __uint_as_float(h);
}
#define FMA2(acc, a, b) asm("fma.rn.f32x2 %0, %1, %2, %0;" : "+l"(acc) : "l"(a), "l"(b))

// ---------------------------------------------------------------------------
// Kernel 1: block 0 folds Wp2@Ww1; blocks 1.. packed-f32x2 fused QKV GEMM.
// (unchanged from measured config)
// ---------------------------------------------------------------------------
__global__ __launch_bounds__(288)
void k1_qkv(const float* __restrict__ feat, int n,
            const float* __restrict__ Wq, const float* __restrict__ bq,
            const float* __restrict__ gq, const float* __restrict__ betaq,
            const float* __restrict__ Wk, const float* __restrict__ bk,
            const float* __restrict__ gk, const float* __restrict__ betak,
            const float* __restrict__ Wv, const float* __restrict__ bv,
            const float* __restrict__ Ww1,
            const float* __restrict__ Wp2, const float* __restrict__ bp2) {
    int t = threadIdx.x;

    if (blockIdx.x == 0) {
        for (int e = t; e < C * G + G; e += 288) {
            if (e < C * G) {
                int j = e / G, g = e % G;
                float acc = 0.f;
                #pragma unroll 8
                for (int c = 0; c < C; c++) acc += Wp2[j * C + c] * Ww1[c * G + g];
                d_Wp2w1[j * G + g] = acc;
            } else {
                int g = e - C * G;
                float acc = 0.f;
                for (int c = 0; c < C; c++) acc += bp2[c] * Ww1[c * G + g];
                d_bp2w1[g] = acc;
            }
        }
        return;
    }

    int base = (blockIdx.x - 1) * TP;

    __shared__ __align__(16) float fsh2[C][TPP];
    __shared__ float qk[2][TP][QKP];

    for (int e = t; e < TP * C; e += 288) {
        int p = e / C, c = e % C;
        int row = base + p; if (row >= n) row = n - 1;
        fsh2[c][p] = feat[row * C + c];
    }
    __syncthreads();

    int m  = t / C;
    int cc = t % C;
    const float* Wm = (m == 0) ? Wq : (m == 1) ? Wk : Wv;

    unsigned long long acc2[TP / 2];
    #pragma unroll
    for (int pp = 0; pp < TP / 2; pp++) acc2[pp] = 0ull;

    #pragma unroll 4
    for (int i = 0; i < C; i++) {
        unsigned long long w2 = bcast2(Wm[i * C + cc]);
        const ulonglong2* frow = (const ulonglong2*)&fsh2[i][0];
        #pragma unroll
        for (int q4 = 0; q4 < TP / 4; q4++) {
            ulonglong2 f = frow[q4];
            FMA2(acc2[q4 * 2    ], f.x, w2);
            FMA2(acc2[q4 * 2 + 1], f.y, w2);
        }
    }

    if (m == 2) {
        float bias = bv[cc];
        #pragma unroll
        for (int pp = 0; pp < TP / 2; pp++) {
            float lo, hi; unpack2(acc2[pp], lo, hi);
            int r0 = base + 2 * pp, r1 = r0 + 1;
            if (r0 < n) d_v[r0 * C + cc] = lo + bias;
            if (r1 < n) d_v[r1 * C + cc] = hi + bias;
        }
    } else {
        float bb = (m == 0) ? bq[cc] : bk[cc];
        float sc = bn_scale((m == 0) ? gq[cc] : gk[cc]);
        float be = (m == 0) ? betaq[cc] : betak[cc];
        #pragma unroll
        for (int pp = 0; pp < TP / 2; pp++) {
            float lo, hi; unpack2(acc2[pp], lo, hi);
            qk[m][2 * pp    ][cc] = fmaxf(fmaf(lo + bb, sc, be), 0.f);
            qk[m][2 * pp + 1][cc] = fmaxf(fmaf(hi + bb, sc, be), 0.f);
        }
    }
    __syncthreads();

    for (int e = t; e < 2 * TP * G; e += 288) {
        int mm  = e / (TP * G);
        int rem = e % (TP * G);
        int p = rem / G, g = rem % G;
        float a = 0.f;
        #pragma unroll 8
        for (int i = 0; i < C; i += 4) {
            float4 qv = *(const float4*)&qk[mm][p][i];
            a = fmaf(qv.x, Ww1[(i    ) * G + g], a);
            a = fmaf(qv.y, Ww1[(i + 1) * G + g], a);
            a = fmaf(qv.z, Ww1[(i + 2) * G + g], a);
            a = fmaf(qv.w, Ww1[(i + 3) * G + g], a);
        }
        int row = base + p;
        if (row < n) {
            if (mm == 0) d_qW[row * G + g] = a;
            else         d_kW[row * G + g] = a;
        }
    }
}

// ---------------------------------------------------------------------------
// Kernel 2: min-wavefront version; phase 5 fused into phase 4 (logits in regs).
// ---------------------------------------------------------------------------
__global__ __launch_bounds__(256, 4)
void k2_main(const float* __restrict__ coord,
             const int*   __restrict__ ref, int n,
             const float* __restrict__ Wp1, const float* __restrict__ bp1,
             const float* __restrict__ gp,  const float* __restrict__ betap,
             const float* __restrict__ Wp2, const float* __restrict__ bp2,
             const float* __restrict__ bw1, const float* __restrict__ gw,
             const float* __restrict__ betaw,
             const float* __restrict__ Ww2, const float* __restrict__ bw2,
             float* __restrict__ out) {
    int nb = blockIdx.x * P;
    int t  = threadIdx.x;
    int lane = t & 31, wid = t >> 5;

    __shared__ float hsh[P * S * CP];                 // 24.8 KB [ps][97]
    __shared__ __align__(16) float Hg[G * HGS];       //  9.3 KB [g][j][4p], padded
    __shared__ __align__(16) float Wsh8[C * 8];       //  3.0 KB Wp2w1 padded to 8/row
    __shared__ __align__(16) unsigned long long wpack[S * G * 2]; // 1.5 KB packed p-pair weights
    __shared__ __align__(16) float4 pos4sh[P * S];    //  1.0 KB
    __shared__ float sWp1[3 * C];
    __shared__ float sA[C], sB[C];
    __shared__ float sWw2[G * G];
    __shared__ float sGw[G], sBw[G], sBw2[G], sBw1c[G];
    __shared__ int   idxsh[P * S];
    __shared__ float msk[P * S];
    __shared__ float kWsh[P * S * G];
    __shared__ float wsh [P * S * G];
    __shared__ float wsum[P * G];
    __shared__ float qWsh[P * G];
    __shared__ float c0[P][3];

    // ---- phase 1: staging
    if (t < P * S) {
        int p = t >> 4, s = t & 15;
        int row = nb + p; if (row >= n) row = n - 1;
        int id = ref[row * S + s];
        idxsh[t] = id;
        int ip1 = id + 1;
        msk[t] = (float)((ip1 > 0) - (ip1 < 0));
    }
    if (t >= 64 && t < 64 + P * 3) {
        int e = t - 64, p = e / 3, d = e % 3;
        int row = nb + p; if (row >= n) row = n - 1;
        c0[p][d] = coord[row * 3 + d];
    }
    if (t >= 96 && t < 96 + P * G) {
        int e = t - 96, p = e / G, g = e % G;
        int row = nb + p; if (row >= n) row = n - 1;
        qWsh[p * G + g] = d_qW[row * G + g];
    }
    if (t >= 128 && t < 128 + G) {
        int g = t - 128;
        sGw[g]   = bn_scale(gw[g]);
        sBw[g]   = betaw[g];
        sBw2[g]  = bw2[g];
        sBw1c[g] = d_bp2w1[g] + bw1[g];
    }
    if (t >= 160 && t < 160 + G * G) sWw2[t - 160] = Ww2[t - 160];
    #pragma unroll
    for (int e = t; e < C * 8; e += 256) {
        int j = e >> 3, kk = e & 7;
        Wsh8[e] = (kk < G) ? d_Wp2w1[j * G + kk] : 0.f;
    }
    if (t < C) {
        float sc = bn_scale(gp[t]);
        sA[t] = sc;
        sB[t] = fmaf(bp1[t], sc, betap[t]);
        sWp1[0 * C + t] = Wp1[0 * C + t];
        sWp1[1 * C + t] = Wp1[1 * C + t];
        sWp1[2 * C + t] = Wp1[2 * C + t];
    }
    __syncthreads();

    // ---- phase 2: pos (packed float4) + kW gathers
    if (t < P * S) {
        int p = t >> 4;
        int id = idxsh[t];
        float4 v;
        v.x = coord[id * 3 + 0] - c0[p][0];
        v.y = coord[id * 3 + 1] - c0[p][1];
        v.z = coord[id * 3 + 2] - c0[p][2];
        v.w = 0.f;
        pos4sh[t] = v;
    }
    for (int e = t; e < P * S * G; e += 256) {
        int ps = e / G, g = e - (e / G) * G;
        kWsh[ps * G + g] = d_kW[idxsh[ps] * G + g];
    }
    __syncthreads();

    // ---- phase 3: h = relu(bn(pos@Wp1)); c-persistent warps, pos bcast as float4
    if (wid < 6) {
        int chunk = wid >> 1, pp = wid & 1;       // c-chunk 0..2, p-pair 0..1
        int c = chunk * 32 + lane;
        float w0 = sWp1[0 * C + c], w1 = sWp1[1 * C + c], w2 = sWp1[2 * C + c];
        float aa = sA[c], bb = sB[c];
        #pragma unroll 4
        for (int s = 0; s < S; s++) {
            #pragma unroll
            for (int pq = 0; pq < 2; pq++) {
                int p = pp * 2 + pq;
                float4 ps4 = pos4sh[p * S + s];
                float h = fmaf(ps4.x, w0, fmaf(ps4.y, w1, ps4.z * w2));
                hsh[(p * S + s) * CP + c] = fmaxf(fmaf(h, aa, bb), 0.f);
            }
        }
    }
    __syncthreads();

    // ---- phase 4+5 fused: relation@Ww1 -> bn -> relu -> logits (all in regs)
    if (t < P * S) {
        int ps = t, p = t >> 4;
        unsigned long long u2[3];
        #pragma unroll
        for (int gp2 = 0; gp2 < 3; gp2++) {
            int g0 = gp2 * 2, g1 = g0 + 1;
            u2[gp2] = pack2(kWsh[ps * G + g0] - qWsh[p * G + g0] + sBw1c[g0],
                            kWsh[ps * G + g1] - qWsh[p * G + g1] + sBw1c[g1]);
        }
        const float* hrow = &hsh[ps * CP];
        #pragma unroll 4
        for (int j = 0; j < C; j++) {
            unsigned long long h2 = bcast2(hrow[j]);
            ulonglong2 wv = *(const ulonglong2*)&Wsh8[j * 8];       // g0..g3
            unsigned long long w45 = *(const unsigned long long*)&Wsh8[j * 8 + 4];
            FMA2(u2[0], h2, wv.x);
            FMA2(u2[1], h2, wv.y);
            FMA2(u2[2], h2, w45);
        }
        float A[G];
        #pragma unroll
        for (int gp2 = 0; gp2 < 3; gp2++) {
            int g0 = gp2 * 2, g1 = g0 + 1;
            float u0, u1; unpack2(u2[gp2], u0, u1);
            A[g0] = fmaxf(fmaf(u0, sGw[g0], sBw[g0]), 0.f);
            A[g1] = fmaxf(fmaf(u1, sGw[g1], sBw[g1]), 0.f);
        }
        // logits = A @ Ww2 + bw2 (register-local A, g2-pairs packed)
        unsigned long long l2[3];
        #pragma unroll
        for (int gp2 = 0; gp2 < 3; gp2++)
            l2[gp2] = pack2(sBw2[gp2 * 2], sBw2[gp2 * 2 + 1]);
        #pragma unroll
        for (int g = 0; g < G; g++) {
            unsigned long long a2 = bcast2(A[g]);
            #pragma unroll
            for (int gp2 = 0; gp2 < 3; gp2++) {
                unsigned long long w2 = *(const unsigned long long*)&sWw2[g * G + gp2 * 2];
                FMA2(l2[gp2], a2, w2);
            }
        }
        #pragma unroll
        for (int gp2 = 0; gp2 < 3; gp2++) {
            float l0, l1; unpack2(l2[gp2], l0, l1);
            wsh[ps * G + gp2 * 2    ] = l0;
            wsh[ps * G + gp2 * 2 + 1] = l1;
        }
    }
    __syncthreads();

    // ---- phase 6: softmax over neighbours + mask
    if (t < P * G) {
        int p = t / G, g = t - (t / G) * G;
        float m = -1e30f;
        #pragma unroll
        for (int s = 0; s < S; s++) m = fmaxf(m, wsh[(p * S + s) * G + g]);
        float sum = 0.f;
        #pragma unroll
        for (int s = 0; s < S; s++) {
            float e = __expf(wsh[(p * S + s) * G + g] - m);
            wsh[(p * S + s) * G + g] = e; sum += e;
        }
        float inv = 1.0f / sum;
        float ws = 0.f;
        #pragma unroll
        for (int s = 0; s < S; s++) {
            float wv = wsh[(p * S + s) * G + g] * inv * msk[p * S + s];
            wsh[(p * S + s) * G + g] = wv; ws += wv;
        }
        wsum[p * G + g] = ws;
    }
    __syncthreads();

    // ---- phase 6b: prepack w as p-pairs for phase 7
    if (t < S * G * 2) {
        int s = t / 12, r = t - (t / 12) * 12, g = r >> 1, pp = r & 1;
        wpack[(s * G + g) * 2 + pp] =
            pack2(wsh[((pp * 2    ) * S + s) * G + g],
                  wsh[((pp * 2 + 1) * S + s) * G + g]);
    }
    __syncthreads();

    // ---- phase 7: Hg[g][j][p] = sum_s w[p,s,g]*h[p,s,j]
    if (wid < 3) {
        int j = wid * 32 + lane;
        unsigned long long acc[12];
        #pragma unroll
        for (int i = 0; i < 12; i++) acc[i] = 0ull;
        #pragma unroll 4
        for (int s = 0; s < S; s++) {
            float h0 = hsh[(0 * S + s) * CP + j];
            float h1 = hsh[(1 * S + s) * CP + j];
            float h2v = hsh[(2 * S + s) * CP + j];
            float h3 = hsh[(3 * S + s) * CP + j];
            unsigned long long h01 = pack2(h0, h1);
            unsigned long long h23 = pack2(h2v, h3);
            #pragma unroll
            for (int g = 0; g < G; g++) {
                ulonglong2 wv = *(const ulonglong2*)&wpack[(s * G + g) * 2];
                FMA2(acc[g * 2    ], h01, wv.x);
                FMA2(acc[g * 2 + 1], h23, wv.y);
            }
        }
        #pragma unroll
        for (int g = 0; g < G; g++) {
            float4 o;
            unpack2(acc[g * 2    ], o.x, o.y);
            unpack2(acc[g * 2 + 1], o.z, o.w);
            *(float4*)&Hg[g * HGS + j * 4] = o;
        }
    }
    __syncthreads();

    // ---- phase 8: out = v-term + Hg@Wp2 + bp2*wsum; 96 threads own all 4 p.
    if (t < C) {
        int c = t, g = c >> 4;
        float bp2c = bp2[c];
        unsigned long long a01 = pack2(bp2c * wsum[0 * G + g], bp2c * wsum[1 * G + g]);
        unsigned long long a23 = pack2(bp2c * wsum[2 * G + g], bp2c * wsum[3 * G + g]);
        #pragma unroll 4
        for (int j = 0; j < C; j++) {
            ulonglong2 hg = *(const ulonglong2*)&Hg[g * HGS + j * 4];  // broadcast, conflict-free
            unsigned long long w2 = bcast2(Wp2[j * C + c]);
            FMA2(a01, hg.x, w2);
            FMA2(a23, hg.y, w2);
        }
        float a0, a1, a2, a3;
        unpack2(a01, a0, a1);
        unpack2(a23, a2, a3);
        #pragma unroll 4
        for (int s = 0; s < S; s++) {
            a0 = fmaf(wsh[(0 * S + s) * G + g], d_v[idxsh[0 * S + s] * C + c], a0);
            a1 = fmaf(wsh[(1 * S + s) * G + g], d_v[idxsh[1 * S + s] * C + c], a1);
            a2 = fmaf(wsh[(2 * S + s) * G + g], d_v[idxsh[2 * S + s] * C + c], a2);
            a3 = fmaf(wsh[(3 * S + s) * G + g], d_v[idxsh[3 * S + s] * C + c], a3);
        }
        int r0 = nb, r1 = nb + 1, r2 = nb + 2, r3 = nb + 3;
        if (r0 < n) out[r0 * C + c] = a0;
        if (r1 < n) out[r1 * C + c] = a1;
        if (r2 < n) out[r2 * C + c] = a2;
        if (r3 < n) out[r3 * C + c] = a3;
    }
}

// ---------------------------------------------------------------------------
extern "C" void kernel_launch(void* const* d_in, const int* in_sizes, int n_in,
                              void* d_out, int out_size) {
    const float* feat   = (const float*)d_in[0];
    const float* coord  = (const float*)d_in[1];
    const int*   refidx = (const int*)  d_in[2];
    const float* Wq = (const float*)d_in[3];  const float* bq = (const float*)d_in[4];
    const float* gq = (const float*)d_in[5];  const float* betaq = (const float*)d_in[6];
    const float* Wk = (const float*)d_in[7];  const float* bk = (const float*)d_in[8];
    const float* gk = (const float*)d_in[9];  const float* betak = (const float*)d_in[10];
    const float* Wv = (const float*)d_in[11]; const float* bv = (const float*)d_in[12];
    const float* Wp1 = (const float*)d_in[13]; const float* bp1 = (const float*)d_in[14];
    const float* gp  = (const float*)d_in[15]; const float* betap = (const float*)d_in[16];
    const float* Wp2 = (const float*)d_in[17]; const float* bp2 = (const float*)d_in[18];
    const float* Ww1 = (const float*)d_in[19]; const float* bw1 = (const float*)d_in[20];
    const float* gw  = (const float*)d_in[21]; const float* betaw = (const float*)d_in[22];
    const float* Ww2 = (const float*)d_in[23]; const float* bw2 = (const float*)d_in[24];
    float* out = (float*)d_out;

    int n = in_sizes[0] / C;   // 50000

    // Max shared-memory carveout so k2's 47KB static smem fits 4 CTAs/SM.
    // Host-side attribute set; not stream-ordered, capture-safe, deterministic.
    cudaFuncSetAttribute(k2_main, cudaFuncAttributePreferredSharedMemoryCarveout, 100);
    cudaFuncSetAttribute(k1_qkv,  cudaFuncAttributePreferredSharedMemoryCarveout, 100);

    k1_qkv<<<1 + (n + TP - 1) / TP, 288>>>(feat, n, Wq, bq, gq, betaq,
                                           Wk, bk, gk, betak, Wv, bv, Ww1,
                                           Wp2, bp2);
    k2_main<<<(n + P - 1) / P, 256>>>(coord, refidx, n, Wp1, bp1, gp, betap,
                                      Wp2, bp2, bw1, gw, betaw, Ww2, bw2, out);
}